// round 9
// baseline (speedup 1.0000x reference)
#include <cuda_runtime.h>
#include <cuda_fp16.h>
#include <cstdint>

// ---------------------------------------------------------------------------
// y[bi,co,ti,p] = sum_{ds,dt,ci} W[co,ci,ds,dt]*x[bi',ci,t2,p] + x
// fp16 mma.sync m16n8k16 (fp32 accum) implicit GEMM.
// Within-32 K-permutation (applied in prep) packs BOTH k16-step fragments of
// a row contiguously -> each fragment load is a single LDS.128, conflict-free
// at PADH=32 (64B rows: phase offsets gid*64 + tig*16 cover all 8 bank-groups).
// Skeleton: 3-stage cp.async, 1 syncthreads/iter, NPAD=200 asymmetric tiles,
// cost-sorted block order.
// ---------------------------------------------------------------------------

#define CCH 1024
#define TT 4
#define HW 196
#define NPAD 200
#define SSEG 4
#define BM 128
#define BN 112
#define BKI 32
#define PADH 32                      // halves per smem row (64B, no padding)
#define STAGES 3

#define ASZH (BM * PADH)             // 4096 halves
#define BSZH (BN * PADH)             // 3584 halves
#define STAGE_BYTES ((ASZH + BSZH) * 2)   // 15360 B
#define SMEM_REQ (STAGES * STAGE_BYTES)   // 46080 B

__device__ __half g_Wt[9u * CCH * CCH];      // [tap][co][perm32(ci)]
__device__ __half g_Xt[32u * NPAD * CCH];    // [z][p][perm32(ci)]

// heavy blocks first: nv=9, then nv=6, then nv=4
__constant__ int c_zorder[32] = {
    5, 6, 9, 10, 21, 22, 25, 26,
    4, 7, 8, 11, 20, 23, 24, 27,
    1, 2, 13, 14, 17, 18, 29, 30,
    0, 3, 12, 15, 16, 19, 28, 31
};

// logical k within 32 -> phys: fragment pair for (tig=t) lands at 8t..8t+7:
//   [8t..8t+3] = ks0 {2t,2t+1,2t+8,2t+9}, [8t+4..8t+7] = ks1 {16+...}
__device__ __forceinline__ int perm32(int ci) {
    int j = ci & 31;
    int t = (j & 7) >> 1, lo = j & 1, hi = (j >> 3) & 1, ks = j >> 4;
    return (ci & ~31) | (8 * t + 4 * ks + 2 * hi + lo);
}

// ---------------------------- helpers --------------------------------------
__device__ __forceinline__ void cp16(uint32_t dst, const void* src) {
    asm volatile("cp.async.cg.shared.global [%0], [%1], 16;" :: "r"(dst), "l"(src));
}
#define CP_COMMIT() asm volatile("cp.async.commit_group;" ::: "memory")
#define CP_WAIT1()  asm volatile("cp.async.wait_group 1;" ::: "memory")

__device__ __forceinline__ void mma_f16(float* c, uint32_t a0, uint32_t a1,
                                        uint32_t a2, uint32_t a3,
                                        uint32_t b0, uint32_t b1) {
    asm volatile(
        "mma.sync.aligned.m16n8k16.row.col.f32.f16.f16.f32 "
        "{%0,%1,%2,%3}, {%4,%5,%6,%7}, {%8,%9}, {%0,%1,%2,%3};"
        : "+f"(c[0]), "+f"(c[1]), "+f"(c[2]), "+f"(c[3])
        : "r"(a0), "r"(a1), "r"(a2), "r"(a3), "r"(b0), "r"(b1));
}

// ---------------------------- merged prep kernel ----------------------------
__global__ __launch_bounds__(256) void prep_all(const float* __restrict__ W,
                                                const float* __restrict__ x) {
    int b = blockIdx.x;
    if (b < 1024) {
        __shared__ float s[9216];
        int co = b;
        const float4* row4 = (const float4*)(W + (size_t)co * 9216);
        float4* s4 = (float4*)s;
        for (int i = threadIdx.x; i < 2304; i += 256) s4[i] = row4[i];
        __syncthreads();
        for (int tap = 0; tap < 9; tap++) {
            __half* d = g_Wt + ((size_t)tap * CCH + co) * CCH;
            for (int ci = threadIdx.x; ci < CCH; ci += 256)
                d[perm32(ci)] = __float2half(s[ci * 9 + tap]);
        }
    } else {
        __shared__ float tile[32][33];
        int bb = b - 1024;
        int pt = bb % 7;
        int cit = (bb / 7) & 31;
        int z = bb / (7 * 32);
        int p0 = pt * 32;
        int ci0 = cit * 32;
        int tx = threadIdx.x & 31, ty = threadIdx.x >> 5;   // 32 x 8
        #pragma unroll
        for (int j = 0; j < 4; j++) {
            int ci = ci0 + ty + j * 8;
            int p = p0 + tx;
            float v = 0.f;
            if (p < HW) v = x[(((size_t)((z >> 2) * CCH + ci)) * TT + (z & 3)) * HW + p];
            tile[ty + j * 8][tx] = v;
        }
        __syncthreads();
        #pragma unroll
        for (int j = 0; j < 4; j++) {
            int p = p0 + ty + j * 8;
            int ci = ci0 + tx;
            if (p < NPAD)
                g_Xt[((size_t)z * NPAD + p) * CCH + perm32(ci)] =
                    __float2half(tile[tx][ty + j * 8]);
        }
    }
}

// ---------------------------- main kernel -----------------------------------
__global__ __launch_bounds__(256, 2) void conv_mma(
    const float* __restrict__ x, float* __restrict__ out)
{
    extern __shared__ __half smem[];
    const int tid = threadIdx.x;
    const int wid = tid >> 5, lid = tid & 31;
    const int gid = lid >> 2, tig = lid & 3;
    const int warp_m = wid & 3;           // 4 warps in M: 32 rows each
    const int warp_n = wid >> 2;          // 2 warps in N

    const int bidl = blockIdx.x;
    const int z    = c_zorder[bidl >> 4];
    const int tile = bidl & 15;
    const int ct   = tile >> 1;           // co-tile 0..7
    const int py   = tile & 1;            // p-tile 0..1
    const int bi = z >> 2, ti = z & 3;
    const int s_seg = bi & 3, bp = bi >> 2;
    const int co0 = ct * BM;
    const int p0  = py * BN;

    const int ntc  = (py && warp_n) ? 4 : 7;   // 112-wide vs 88-wide tile
    const int bnr4 = (py ? 88 : 112) * 4;      // B 16B-chunks per stage

    int taps[9], zsrc[9], nv = 0;
    #pragma unroll
    for (int ds = 0; ds < 3; ds++) {
        int s2 = s_seg + ds - 1;
        if (s2 < 0 || s2 >= SSEG) continue;
        #pragma unroll
        for (int dt = 0; dt < 3; dt++) {
            int t2 = ti + dt - 1;
            if (t2 < 0 || t2 >= TT) continue;
            taps[nv] = ds * 3 + dt;
            zsrc[nv] = (bp * SSEG + s2) * TT + t2;
            nv++;
        }
    }
    const int total = nv * (CCH / BKI);

    uint32_t smem_u = (uint32_t)__cvta_generic_to_shared(smem);

    float acc[2][7][4];
    #pragma unroll
    for (int mt = 0; mt < 2; mt++)
        #pragma unroll
        for (int nt = 0; nt < 7; nt++)
            #pragma unroll
            for (int r = 0; r < 4; r++) acc[mt][nt][r] = 0.f;

    auto load_stage = [&](int it, int st) {
        int idx = it >> 5, k0 = (it & 31) * BKI;
        const __half* Wt = g_Wt + (size_t)taps[idx] * CCH * CCH + (size_t)co0 * CCH + k0;
        const __half* Xz = g_Xt + (size_t)zsrc[idx] * NPAD * CCH + (size_t)p0 * CCH + k0;
        uint32_t aB = smem_u + st * STAGE_BYTES;
        uint32_t bB = aB + ASZH * 2;
        #pragma unroll
        for (int i = 0; i < 2; i++) {
            int c = tid + i * 256;               // 512 A chunks (128 rows x 4)
            int row = c >> 2, cc = c & 3;
            cp16(aB + row * (PADH * 2) + cc * 16, Wt + (size_t)row * CCH + cc * 8);
        }
        #pragma unroll
        for (int i = 0; i < 2; i++) {
            int c = tid + i * 256;
            if (c < bnr4) {
                int row = c >> 2, cc = c & 3;
                cp16(bB + row * (PADH * 2) + cc * 16, Xz + (size_t)row * CCH + cc * 8);
            }
        }
    };

    load_stage(0, 0); CP_COMMIT();
    load_stage(1, 1); CP_COMMIT();

    int st = 0;
    for (int it = 0; it < total; it++) {
        CP_WAIT1();
        __syncthreads();           // stage (st+2)%3 now free for refill

        int nxst = st + 2; if (nxst >= STAGES) nxst -= STAGES;
        if (it + 2 < total) load_stage(it + 2, nxst);
        CP_COMMIT();

        const __half* As = smem + (size_t)st * (ASZH + BSZH);
        const __half* Bs = As + ASZH;
        const int ko = tig * 8;               // phys half offset of dual fragment

        // one LDS.128 per fragment: covers both k16 steps
        uint4 a0[2], a1[2], bv[7];
        #pragma unroll
        for (int mt = 0; mt < 2; mt++) {
            int r0 = warp_m * 32 + mt * 16 + gid;
            a0[mt] = *(const uint4*)(As + r0 * PADH + ko);
            a1[mt] = *(const uint4*)(As + (r0 + 8) * PADH + ko);
        }
        #pragma unroll
        for (int nt = 0; nt < 7; nt++)
            if (nt < ntc)
                bv[nt] = *(const uint4*)(Bs + (warp_n * 56 + nt * 8 + gid) * PADH + ko);

        // ks = 0 (x,y components), then ks = 1 (z,w components)
        #pragma unroll
        for (int mt = 0; mt < 2; mt++)
            #pragma unroll
            for (int nt = 0; nt < 7; nt++)
                if (nt < ntc)
                    mma_f16(acc[mt][nt], a0[mt].x, a1[mt].x, a0[mt].y, a1[mt].y,
                            bv[nt].x, bv[nt].y);
        #pragma unroll
        for (int mt = 0; mt < 2; mt++)
            #pragma unroll
            for (int nt = 0; nt < 7; nt++)
                if (nt < ntc)
                    mma_f16(acc[mt][nt], a0[mt].z, a1[mt].z, a0[mt].w, a1[mt].w,
                            bv[nt].z, bv[nt].w);

        st = st + 1; if (st >= STAGES) st = 0;
    }

    // epilogue: residual add + store
    #pragma unroll
    for (int mt = 0; mt < 2; mt++) {
        #pragma unroll
        for (int nt = 0; nt < 7; nt++) {
            if (nt >= ntc) continue;
            int co = co0 + warp_m * 32 + mt * 16 + gid;
            int p  = p0 + warp_n * 56 + nt * 8 + tig * 2;
            if (p < HW) {
                size_t i0 = ((size_t)(bi * CCH + co) * TT + ti) * HW + p;
                float2 r0 = *(const float2*)&x[i0];
                float2 o0 = { acc[mt][nt][0] + r0.x, acc[mt][nt][1] + r0.y };
                *(float2*)&out[i0] = o0;
                size_t i1 = ((size_t)(bi * CCH + co + 8) * TT + ti) * HW + p;
                float2 r1 = *(const float2*)&x[i1];
                float2 o1 = { acc[mt][nt][2] + r1.x, acc[mt][nt][3] + r1.y };
                *(float2*)&out[i1] = o1;
            }
        }
    }
}

// ---------------------------- host launch -----------------------------------
extern "C" void kernel_launch(void* const* d_in, const int* in_sizes, int n_in,
                              void* d_out, int out_size) {
    const float* x = (const float*)d_in[0];   // (8,1024,4,14,14)
    const float* W = (const float*)d_in[1];   // (1024,1024,3,3)
    float* out = (float*)d_out;

    prep_all<<<1024 + 7 * 32 * 32, 256>>>(W, x);

    cudaFuncSetAttribute(conv_mma, cudaFuncAttributeMaxDynamicSharedMemorySize, SMEM_REQ);
    conv_mma<<<512, 256, SMEM_REQ>>>(x, out);
}

// round 11
// speedup vs baseline: 1.0524x; 1.0524x over previous
#include <cuda_runtime.h>
#include <cuda_fp16.h>
#include <cstdint>

// ---------------------------------------------------------------------------
// y[bi,co,ti,p] = sum_{ds,dt,ci} W[co,ci,ds,dt]*x[bi',ci,t2,p] + x
// fp16 mma.sync m16n8k16 (fp32 accum) implicit GEMM.
// R9 base (perm32 K-permutation -> LDS.128 fragments, conflict-free 64B rows,
// NPAD=200 asymmetric tiles, cost-sorted blocks) with BK=64 per pipeline
// stage: two independent k32 sub-tiles per stage (each keeping the proven
// PADH=32 layout), halving barrier/wait frequency. Discriminates
// overhead-bound vs HMMA-ceiling-bound. (Resubmit of R10 — infra failure,
// kernel never ran; source re-verified by inspection.)
// ---------------------------------------------------------------------------

#define CCH 1024
#define TT 4
#define HW 196
#define NPAD 200
#define SSEG 4
#define BM 128
#define BN 112
#define PADH 32                        // halves per sub-tile row (64B)
#define STAGES 3

#define ASUBH (BM * PADH)              // 4096 halves per A sub-tile
#define BSUBH (BN * PADH)              // 3584 halves per B sub-tile
#define STAGE_H (2 * (ASUBH + BSUBH))  // 15360 halves per stage (BK=64)
#define STAGE_BYTES (STAGE_H * 2)      // 30720 B
#define SMEM_REQ (STAGES * STAGE_BYTES)   // 92160 B

__device__ __half g_Wt[9u * CCH * CCH];      // [tap][co][perm32(ci)]
__device__ __half g_Xt[32u * NPAD * CCH];    // [z][p][perm32(ci)]

// heavy blocks first: nv=9, then nv=6, then nv=4
__constant__ int c_zorder[32] = {
    5, 6, 9, 10, 21, 22, 25, 26,
    4, 7, 8, 11, 20, 23, 24, 27,
    1, 2, 13, 14, 17, 18, 29, 30,
    0, 3, 12, 15, 16, 19, 28, 31
};

// logical k within 32 -> phys: fragment pair for (tig=t) lands at 8t..8t+7
__device__ __forceinline__ int perm32(int ci) {
    int j = ci & 31;
    int t = (j & 7) >> 1, lo = j & 1, hi = (j >> 3) & 1, ks = j >> 4;
    return (ci & ~31) | (8 * t + 4 * ks + 2 * hi + lo);
}

// ---------------------------- helpers --------------------------------------
__device__ __forceinline__ void cp16(uint32_t dst, const void* src) {
    asm volatile("cp.async.cg.shared.global [%0], [%1], 16;" :: "r"(dst), "l"(src));
}
#define CP_COMMIT() asm volatile("cp.async.commit_group;" ::: "memory")
#define CP_WAIT1()  asm volatile("cp.async.wait_group 1;" ::: "memory")

__device__ __forceinline__ void mma_f16(float* c, uint32_t a0, uint32_t a1,
                                        uint32_t a2, uint32_t a3,
                                        uint32_t b0, uint32_t b1) {
    asm volatile(
        "mma.sync.aligned.m16n8k16.row.col.f32.f16.f16.f32 "
        "{%0,%1,%2,%3}, {%4,%5,%6,%7}, {%8,%9}, {%0,%1,%2,%3};"
        : "+f"(c[0]), "+f"(c[1]), "+f"(c[2]), "+f"(c[3])
        : "r"(a0), "r"(a1), "r"(a2), "r"(a3), "r"(b0), "r"(b1));
}

// ---------------------------- merged prep kernel ----------------------------
__global__ __launch_bounds__(256) void prep_all(const float* __restrict__ W,
                                                const float* __restrict__ x) {
    int b = blockIdx.x;
    if (b < 1024) {
        __shared__ float s[9216];
        int co = b;
        const float4* row4 = (const float4*)(W + (size_t)co * 9216);
        float4* s4 = (float4*)s;
        for (int i = threadIdx.x; i < 2304; i += 256) s4[i] = row4[i];
        __syncthreads();
        for (int tap = 0; tap < 9; tap++) {
            __half* d = g_Wt + ((size_t)tap * CCH + co) * CCH;
            for (int ci = threadIdx.x; ci < CCH; ci += 256)
                d[perm32(ci)] = __float2half(s[ci * 9 + tap]);
        }
    } else {
        __shared__ float tile[32][33];
        int bb = b - 1024;
        int pt = bb % 7;
        int cit = (bb / 7) & 31;
        int z = bb / (7 * 32);
        int p0 = pt * 32;
        int ci0 = cit * 32;
        int tx = threadIdx.x & 31, ty = threadIdx.x >> 5;   // 32 x 8
        #pragma unroll
        for (int j = 0; j < 4; j++) {
            int ci = ci0 + ty + j * 8;
            int p = p0 + tx;
            float v = 0.f;
            if (p < HW) v = x[(((size_t)((z >> 2) * CCH + ci)) * TT + (z & 3)) * HW + p];
            tile[ty + j * 8][tx] = v;
        }
        __syncthreads();
        #pragma unroll
        for (int j = 0; j < 4; j++) {
            int p = p0 + ty + j * 8;
            int ci = ci0 + tx;
            if (p < NPAD)
                g_Xt[((size_t)z * NPAD + p) * CCH + perm32(ci)] =
                    __float2half(tile[tx][ty + j * 8]);
        }
    }
}

// ---------------------------- main kernel -----------------------------------
__global__ __launch_bounds__(256, 2) void conv_mma(
    const float* __restrict__ x, float* __restrict__ out)
{
    extern __shared__ __half smem[];
    const int tid = threadIdx.x;
    const int wid = tid >> 5, lid = tid & 31;
    const int gid = lid >> 2, tig = lid & 3;
    const int warp_m = wid & 3;           // 4 warps in M: 32 rows each
    const int warp_n = wid >> 2;          // 2 warps in N

    const int bidl = blockIdx.x;
    const int z    = c_zorder[bidl >> 4];
    const int tile = bidl & 15;
    const int ct   = tile >> 1;           // co-tile 0..7
    const int py   = tile & 1;            // p-tile 0..1
    const int bi = z >> 2, ti = z & 3;
    const int s_seg = bi & 3, bp = bi >> 2;
    const int co0 = ct * BM;
    const int p0  = py * BN;

    const int ntc  = (py && warp_n) ? 4 : 7;   // 112-wide vs 88-wide tile
    const int bnr8 = (py ? 88 : 112) * 8;      // B 16B-chunks per stage (BK=64)

    int taps[9], zsrc[9], nv = 0;
    #pragma unroll
    for (int ds = 0; ds < 3; ds++) {
        int s2 = s_seg + ds - 1;
        if (s2 < 0 || s2 >= SSEG) continue;
        #pragma unroll
        for (int dt = 0; dt < 3; dt++) {
            int t2 = ti + dt - 1;
            if (t2 < 0 || t2 >= TT) continue;
            taps[nv] = ds * 3 + dt;
            zsrc[nv] = (bp * SSEG + s2) * TT + t2;
            nv++;
        }
    }
    const int total = nv * (CCH / 64);    // BK=64 iters

    uint32_t smem_u = (uint32_t)__cvta_generic_to_shared(smem);

    float acc[2][7][4];
    #pragma unroll
    for (int mt = 0; mt < 2; mt++)
        #pragma unroll
        for (int nt = 0; nt < 7; nt++)
            #pragma unroll
            for (int r = 0; r < 4; r++) acc[mt][nt][r] = 0.f;

    auto load_stage = [&](int it, int st) {
        int idx = it >> 4, k0 = (it & 15) * 64;
        const __half* Wt = g_Wt + (size_t)taps[idx] * CCH * CCH + (size_t)co0 * CCH + k0;
        const __half* Xz = g_Xt + (size_t)zsrc[idx] * NPAD * CCH + (size_t)p0 * CCH + k0;
        uint32_t aB = smem_u + st * STAGE_BYTES;
        uint32_t bB = aB + 2 * ASUBH * 2;
        // A: 1024 chunks (128 rows x 8), 4 per thread
        #pragma unroll
        for (int i = 0; i < 4; i++) {
            int c = tid + i * 256;
            int row = c >> 3, cc = c & 7;
            int kb = cc >> 2, c4 = cc & 3;
            cp16(aB + kb * (ASUBH * 2) + row * 64 + c4 * 16,
                 Wt + (size_t)row * CCH + kb * 32 + c4 * 8);
        }
        // B: up to 896 chunks (112 rows x 8)
        #pragma unroll
        for (int i = 0; i < 4; i++) {
            int c = tid + i * 256;
            if (c < bnr8) {
                int row = c >> 3, cc = c & 7;
                int kb = cc >> 2, c4 = cc & 3;
                cp16(bB + kb * (BSUBH * 2) + row * 64 + c4 * 16,
                     Xz + (size_t)row * CCH + kb * 32 + c4 * 8);
            }
        }
    };

    load_stage(0, 0); CP_COMMIT();
    load_stage(1, 1); CP_COMMIT();

    int st = 0;
    for (int it = 0; it < total; it++) {
        CP_WAIT1();
        __syncthreads();           // stage (st+2)%3 now free for refill

        int nxst = st + 2; if (nxst >= STAGES) nxst -= STAGES;
        if (it + 2 < total) load_stage(it + 2, nxst);
        CP_COMMIT();

        const __half* As0 = smem + (size_t)st * STAGE_H;
        const int ko = tig * 8;

        #pragma unroll
        for (int kb = 0; kb < 2; kb++) {
            const __half* Ak = As0 + kb * ASUBH;
            const __half* Bk = As0 + 2 * ASUBH + kb * BSUBH;

            uint4 a0[2], a1[2], bv[7];
            #pragma unroll
            for (int mt = 0; mt < 2; mt++) {
                int r0 = warp_m * 32 + mt * 16 + gid;
                a0[mt] = *(const uint4*)(Ak + r0 * PADH + ko);
                a1[mt] = *(const uint4*)(Ak + (r0 + 8) * PADH + ko);
            }
            #pragma unroll
            for (int nt = 0; nt < 7; nt++)
                if (nt < ntc)
                    bv[nt] = *(const uint4*)(Bk + (warp_n * 56 + nt * 8 + gid) * PADH + ko);

            #pragma unroll
            for (int mt = 0; mt < 2; mt++)
                #pragma unroll
                for (int nt = 0; nt < 7; nt++)
                    if (nt < ntc)
                        mma_f16(acc[mt][nt], a0[mt].x, a1[mt].x, a0[mt].y, a1[mt].y,
                                bv[nt].x, bv[nt].y);
            #pragma unroll
            for (int mt = 0; mt < 2; mt++)
                #pragma unroll
                for (int nt = 0; nt < 7; nt++)
                    if (nt < ntc)
                        mma_f16(acc[mt][nt], a0[mt].z, a1[mt].z, a0[mt].w, a1[mt].w,
                                bv[nt].z, bv[nt].w);
        }
        st = st + 1; if (st >= STAGES) st = 0;
    }

    // epilogue: residual add + store
    #pragma unroll
    for (int mt = 0; mt < 2; mt++) {
        #pragma unroll
        for (int nt = 0; nt < 7; nt++) {
            if (nt >= ntc) continue;
            int co = co0 + warp_m * 32 + mt * 16 + gid;
            int p  = p0 + warp_n * 56 + nt * 8 + tig * 2;
            if (p < HW) {
                size_t i0 = ((size_t)(bi * CCH + co) * TT + ti) * HW + p;
                float2 r0 = *(const float2*)&x[i0];
                float2 o0 = { acc[mt][nt][0] + r0.x, acc[mt][nt][1] + r0.y };
                *(float2*)&out[i0] = o0;
                size_t i1 = ((size_t)(bi * CCH + co + 8) * TT + ti) * HW + p;
                float2 r1 = *(const float2*)&x[i1];
                float2 o1 = { acc[mt][nt][2] + r1.x, acc[mt][nt][3] + r1.y };
                *(float2*)&out[i1] = o1;
            }
        }
    }
}

// ---------------------------- host launch -----------------------------------
extern "C" void kernel_launch(void* const* d_in, const int* in_sizes, int n_in,
                              void* d_out, int out_size) {
    const float* x = (const float*)d_in[0];   // (8,1024,4,14,14)
    const float* W = (const float*)d_in[1];   // (1024,1024,3,3)
    float* out = (float*)d_out;

    prep_all<<<1024 + 7 * 32 * 32, 256>>>(W, x);

    cudaFuncSetAttribute(conv_mma, cudaFuncAttributeMaxDynamicSharedMemorySize, SMEM_REQ);
    conv_mma<<<512, 256, SMEM_REQ>>>(x, out);
}

// round 13
// speedup vs baseline: 1.0569x; 1.0043x over previous
#include <cuda_runtime.h>
#include <cuda_fp16.h>
#include <cstdint>

// ---------------------------------------------------------------------------
// y[bi,co,ti,p] = sum_{ds,dt,ci} W[co,ci,ds,dt]*x[bi',ci,t2,p] + x
// fp16 mma.sync m16n8k16 (fp32 accum) implicit GEMM. BK=64 stages (two k32
// sub-tiles, proven conflict-free 64B-row layout + perm32 -> LDS.128 frags).
// R12: kb-phase stagger across warps (decorrelate crossbar/tensor bursts),
// uniform-branch ntc specialization (guard-free unrolled MMA bodies),
// hoisted cp.async / LDS offset computation.
// (Resubmit — infra failure, kernel never ran; source re-verified.)
// ---------------------------------------------------------------------------

#define CCH 1024
#define TT 4
#define HW 196
#define NPAD 200
#define SSEG 4
#define BM 128
#define BN 112
#define PADH 32                        // halves per sub-tile row (64B)
#define STAGES 3

#define ASUBH (BM * PADH)              // 4096 halves per A sub-tile
#define BSUBH (BN * PADH)              // 3584 halves per B sub-tile
#define STAGE_H (2 * (ASUBH + BSUBH))  // 15360 halves per stage (BK=64)
#define STAGE_BYTES (STAGE_H * 2)      // 30720 B
#define SMEM_REQ (STAGES * STAGE_BYTES)   // 92160 B

__device__ __half g_Wt[9u * CCH * CCH];      // [tap][co][perm32(ci)]
__device__ __half g_Xt[32u * NPAD * CCH];    // [z][p][perm32(ci)]

__constant__ int c_zorder[32] = {
    5, 6, 9, 10, 21, 22, 25, 26,
    4, 7, 8, 11, 20, 23, 24, 27,
    1, 2, 13, 14, 17, 18, 29, 30,
    0, 3, 12, 15, 16, 19, 28, 31
};

__device__ __forceinline__ int perm32(int ci) {
    int j = ci & 31;
    int t = (j & 7) >> 1, lo = j & 1, hi = (j >> 3) & 1, ks = j >> 4;
    return (ci & ~31) | (8 * t + 4 * ks + 2 * hi + lo);
}

// ---------------------------- helpers --------------------------------------
__device__ __forceinline__ void cp16(uint32_t dst, const void* src) {
    asm volatile("cp.async.cg.shared.global [%0], [%1], 16;" :: "r"(dst), "l"(src));
}
#define CP_COMMIT() asm volatile("cp.async.commit_group;" ::: "memory")
#define CP_WAIT1()  asm volatile("cp.async.wait_group 1;" ::: "memory")

__device__ __forceinline__ void mma_f16(float* c, uint32_t a0, uint32_t a1,
                                        uint32_t a2, uint32_t a3,
                                        uint32_t b0, uint32_t b1) {
    asm volatile(
        "mma.sync.aligned.m16n8k16.row.col.f32.f16.f16.f32 "
        "{%0,%1,%2,%3}, {%4,%5,%6,%7}, {%8,%9}, {%0,%1,%2,%3};"
        : "+f"(c[0]), "+f"(c[1]), "+f"(c[2]), "+f"(c[3])
        : "r"(a0), "r"(a1), "r"(a2), "r"(a3), "r"(b0), "r"(b1));
}

// ---------------------------- merged prep kernel ----------------------------
__global__ __launch_bounds__(256) void prep_all(const float* __restrict__ W,
                                                const float* __restrict__ x) {
    int b = blockIdx.x;
    if (b < 1024) {
        __shared__ float s[9216];
        int co = b;
        const float4* row4 = (const float4*)(W + (size_t)co * 9216);
        float4* s4 = (float4*)s;
        for (int i = threadIdx.x; i < 2304; i += 256) s4[i] = row4[i];
        __syncthreads();
        for (int tap = 0; tap < 9; tap++) {
            __half* d = g_Wt + ((size_t)tap * CCH + co) * CCH;
            for (int ci = threadIdx.x; ci < CCH; ci += 256)
                d[perm32(ci)] = __float2half(s[ci * 9 + tap]);
        }
    } else {
        __shared__ float tile[32][33];
        int bb = b - 1024;
        int pt = bb % 7;
        int cit = (bb / 7) & 31;
        int z = bb / (7 * 32);
        int p0 = pt * 32;
        int ci0 = cit * 32;
        int tx = threadIdx.x & 31, ty = threadIdx.x >> 5;   // 32 x 8
        #pragma unroll
        for (int j = 0; j < 4; j++) {
            int ci = ci0 + ty + j * 8;
            int p = p0 + tx;
            float v = 0.f;
            if (p < HW) v = x[(((size_t)((z >> 2) * CCH + ci)) * TT + (z & 3)) * HW + p];
            tile[ty + j * 8][tx] = v;
        }
        __syncthreads();
        #pragma unroll
        for (int j = 0; j < 4; j++) {
            int p = p0 + ty + j * 8;
            int ci = ci0 + tx;
            if (p < NPAD)
                g_Xt[((size_t)z * NPAD + p) * CCH + perm32(ci)] =
                    __float2half(tile[tx][ty + j * 8]);
        }
    }
}

// ---------------------------- main kernel -----------------------------------
__global__ __launch_bounds__(256, 2) void conv_mma(
    const float* __restrict__ x, float* __restrict__ out)
{
    extern __shared__ __half smem[];
    const int tid = threadIdx.x;
    const int wid = tid >> 5, lid = tid & 31;
    const int gid = lid >> 2, tig = lid & 3;
    const int warp_m = wid & 3;           // 4 warps in M: 32 rows each
    const int warp_n = wid >> 2;          // 2 warps in N

    const int bidl = blockIdx.x;
    const int z    = c_zorder[bidl >> 4];
    const int tile = bidl & 15;
    const int ct   = tile >> 1;           // co-tile 0..7
    const int py   = tile & 1;            // p-tile 0..1
    const int bi = z >> 2, ti = z & 3;
    const int s_seg = bi & 3, bp = bi >> 2;
    const int co0 = ct * BM;
    const int p0  = py * BN;

    const int ntc  = (py && warp_n) ? 4 : 7;   // 112-wide vs 88-wide tile
    const int bnr8 = (py ? 88 : 112) * 8;      // B 16B-chunks per stage

    int taps[9], zsrc[9], nv = 0;
    #pragma unroll
    for (int ds = 0; ds < 3; ds++) {
        int s2 = s_seg + ds - 1;
        if (s2 < 0 || s2 >= SSEG) continue;
        #pragma unroll
        for (int dt = 0; dt < 3; dt++) {
            int t2 = ti + dt - 1;
            if (t2 < 0 || t2 >= TT) continue;
            taps[nv] = ds * 3 + dt;
            zsrc[nv] = (bp * SSEG + s2) * TT + t2;
            nv++;
        }
    }
    const int total = nv * (CCH / 64);    // BK=64 iters

    uint32_t smem_u = (uint32_t)__cvta_generic_to_shared(smem);

    // ---- hoisted per-thread cp.async offsets (iteration-invariant) ----
    uint32_t a_sm[4]; int a_g[4];
    uint32_t b_sm[4]; int b_g[4]; bool b_ok[4];
    #pragma unroll
    for (int i = 0; i < 4; i++) {
        int c = tid + i * 256;
        int row = c >> 3, cc = c & 7;
        int kb = cc >> 2, c4 = cc & 3;
        a_sm[i] = kb * (ASUBH * 2) + row * 64 + c4 * 16;
        a_g[i]  = row * CCH + kb * 32 + c4 * 8;
        b_sm[i] = 2 * (ASUBH * 2) + kb * (BSUBH * 2) + row * 64 + c4 * 16;
        b_g[i]  = row * CCH + kb * 32 + c4 * 8;
        b_ok[i] = (c < bnr8);
    }

    // ---- hoisted per-warp LDS fragment offsets (halves, within sub-tile) ----
    const int ko = tig * 8;
    int aoff0[2], aoff1[2], boff[7];
    #pragma unroll
    for (int mt = 0; mt < 2; mt++) {
        int r0 = warp_m * 32 + mt * 16 + gid;
        aoff0[mt] = r0 * PADH + ko;
        aoff1[mt] = (r0 + 8) * PADH + ko;
    }
    #pragma unroll
    for (int nt = 0; nt < 7; nt++)
        boff[nt] = (warp_n * 56 + nt * 8 + gid) * PADH + ko;

    float acc[2][7][4];
    #pragma unroll
    for (int mt = 0; mt < 2; mt++)
        #pragma unroll
        for (int nt = 0; nt < 7; nt++)
            #pragma unroll
            for (int r = 0; r < 4; r++) acc[mt][nt][r] = 0.f;

    auto load_stage = [&](int it, int st) {
        int idx = it >> 4, k0 = (it & 15) * 64;
        const __half* Wt = g_Wt + (size_t)taps[idx] * CCH * CCH + (size_t)co0 * CCH + k0;
        const __half* Xz = g_Xt + (size_t)zsrc[idx] * NPAD * CCH + (size_t)p0 * CCH + k0;
        uint32_t base = smem_u + st * STAGE_BYTES;
        #pragma unroll
        for (int i = 0; i < 4; i++)
            cp16(base + a_sm[i], Wt + a_g[i]);
        #pragma unroll
        for (int i = 0; i < 4; i++)
            if (b_ok[i]) cp16(base + b_sm[i], Xz + b_g[i]);
    };

    // kb processing order staggered by warp parity to decorrelate LDS bursts
    const int kb_first = wid & 1;

    // guard-free kb body; ntcount is a literal at both call sites
    auto do_kb = [&](const __half* S, int kb, int ntcount) {
        const __half* Ak = S + kb * ASUBH;
        const __half* Bk = S + 2 * ASUBH + kb * BSUBH;
        uint4 a0[2], a1[2], bv[7];
        #pragma unroll
        for (int mt = 0; mt < 2; mt++) {
            a0[mt] = *(const uint4*)(Ak + aoff0[mt]);
            a1[mt] = *(const uint4*)(Ak + aoff1[mt]);
        }
        #pragma unroll
        for (int nt = 0; nt < 7; nt++)
            if (nt < ntcount)
                bv[nt] = *(const uint4*)(Bk + boff[nt]);
        #pragma unroll
        for (int mt = 0; mt < 2; mt++)
            #pragma unroll
            for (int nt = 0; nt < 7; nt++)
                if (nt < ntcount)
                    mma_f16(acc[mt][nt], a0[mt].x, a1[mt].x, a0[mt].y, a1[mt].y,
                            bv[nt].x, bv[nt].y);
        #pragma unroll
        for (int mt = 0; mt < 2; mt++)
            #pragma unroll
            for (int nt = 0; nt < 7; nt++)
                if (nt < ntcount)
                    mma_f16(acc[mt][nt], a0[mt].z, a1[mt].z, a0[mt].w, a1[mt].w,
                            bv[nt].z, bv[nt].w);
    };

    load_stage(0, 0); CP_COMMIT();
    load_stage(1, 1); CP_COMMIT();

    int st = 0;
    for (int it = 0; it < total; it++) {
        CP_WAIT1();
        __syncthreads();           // stage (st+2)%3 now free for refill

        int nxst = st + 2; if (nxst >= STAGES) nxst -= STAGES;
        if (it + 2 < total) load_stage(it + 2, nxst);
        CP_COMMIT();

        const __half* S = smem + (size_t)st * STAGE_H;
        if (ntc == 7) {            // uniform branch, once per iter
            do_kb(S, kb_first, 7);
            do_kb(S, kb_first ^ 1, 7);
        } else {
            do_kb(S, kb_first, 4);
            do_kb(S, kb_first ^ 1, 4);
        }
        st = st + 1; if (st >= STAGES) st = 0;
    }

    // epilogue: residual add + store
    #pragma unroll
    for (int mt = 0; mt < 2; mt++) {
        #pragma unroll
        for (int nt = 0; nt < 7; nt++) {
            if (nt >= ntc) continue;
            int co = co0 + warp_m * 32 + mt * 16 + gid;
            int p  = p0 + warp_n * 56 + nt * 8 + tig * 2;
            if (p < HW) {
                size_t i0 = ((size_t)(bi * CCH + co) * TT + ti) * HW + p;
                float2 r0 = *(const float2*)&x[i0];
                float2 o0 = { acc[mt][nt][0] + r0.x, acc[mt][nt][1] + r0.y };
                *(float2*)&out[i0] = o0;
                size_t i1 = ((size_t)(bi * CCH + co + 8) * TT + ti) * HW + p;
                float2 r1 = *(const float2*)&x[i1];
                float2 o1 = { acc[mt][nt][2] + r1.x, acc[mt][nt][3] + r1.y };
                *(float2*)&out[i1] = o1;
            }
        }
    }
}

// ---------------------------- host launch -----------------------------------
extern "C" void kernel_launch(void* const* d_in, const int* in_sizes, int n_in,
                              void* d_out, int out_size) {
    const float* x = (const float*)d_in[0];   // (8,1024,4,14,14)
    const float* W = (const float*)d_in[1];   // (1024,1024,3,3)
    float* out = (float*)d_out;

    prep_all<<<1024 + 7 * 32 * 32, 256>>>(W, x);

    cudaFuncSetAttribute(conv_mma, cudaFuncAttributeMaxDynamicSharedMemorySize, SMEM_REQ);
    conv_mma<<<512, 256, SMEM_REQ>>>(x, out);
}